// round 4
// baseline (speedup 1.0000x reference)
#include <cuda_runtime.h>

#define B_ROWS   8192
#define NBINS    125
#define M_CAND   4096
#define NTOT     (NBINS * M_CAND)
#define NTHREADS 256
#define EARTH_R  3958.8f
#define DEG2RAD  0.017453292519943295f
#define LSE_T    20.0f   /* exp window: exp(-20)=2e-9, negligible vs 1e-3 tol */

// Static scratch (no allocations allowed)
__device__ float2 g_xy[NTOT];     // candidate unit-vector (x, y)
__device__ float  g_z [NTOT];     // candidate unit-vector z
__device__ float  g_soft [B_ROWS];
__device__ float  g_valid[B_ROWS];
__device__ int    g_ticket;

// ---------------------------------------------------------------------------
// Kernel 1: convert all candidates (lon, lat) deg -> 3D unit vectors.
// Also resets the completion ticket for this call.
// ---------------------------------------------------------------------------
__global__ __launch_bounds__(256)
void precompute_xyz_kernel(const float2* __restrict__ bin_coords) {
    int i = blockIdx.x * 256 + threadIdx.x;
    if (i == 0) g_ticket = 0;
    if (i >= NTOT) return;
    float2 c = bin_coords[i];             // (lon, lat) in degrees
    float lon = c.x * DEG2RAD;
    float lat = c.y * DEG2RAD;
    float slat, clat, slon, clon;
    __sincosf(lat, &slat, &clat);
    __sincosf(lon, &slon, &clon);
    g_xy[i] = make_float2(clat * clon, clat * slon);
    g_z[i]  = slat;
}

// ---------------------------------------------------------------------------
// Kernel 2: per-row soft-min via chord-space streaming + threshold skip,
// with fused final reduction in the last block to finish.
// ---------------------------------------------------------------------------
__global__ __launch_bounds__(NTHREADS)
void softbin_main_kernel(const float* __restrict__ preds,
                         const long long* __restrict__ x_vals,
                         const long long* __restrict__ bin_counts,
                         float* __restrict__ out) {
    const int b   = blockIdx.x;
    const int tid = threadIdx.x;

    __shared__ float sh_p[3];         // pred unit vector
    __shared__ int   sh_meta[2];      // bin base index, count

    if (tid == 0) {
        long long bin_id = x_vals[b * 3 + 0] * 25 + x_vals[b * 3 + 1] * 5 + x_vals[b * 3 + 2];
        if (bin_id < 0) bin_id = 0;
        if (bin_id >= NBINS) bin_id = NBINS - 1;
        int count = (int)bin_counts[bin_id];
        if (count > M_CAND) count = M_CAND;
        sh_meta[0] = (int)bin_id * M_CAND;
        sh_meta[1] = count;
        float lon = preds[b * 2 + 0] * DEG2RAD;
        float lat = preds[b * 2 + 1] * DEG2RAD;
        float slat, clat, slon, clon;
        __sincosf(lat, &slat, &clat);
        __sincosf(lon, &slon, &clon);
        sh_p[0] = clat * clon;
        sh_p[1] = clat * slon;
        sh_p[2] = slat;
    }
    __syncthreads();

    const int   base  = sh_meta[0];
    const int   count = sh_meta[1];
    const float px = sh_p[0], py = sh_p[1], pz = sh_p[2];

    const float2* __restrict__ cxy = g_xy + base;
    const float*  __restrict__ cz  = g_z  + base;

    // Online logsumexp over logits l = -4 * d  (d = 2R asin(|chord|/2))
    float m = -3.0e38f;
    float s = 0.0f;
    float s2_th = 5.0f;                   // accept all (max chord^2 = 4)

    #pragma unroll 2
    for (int j = tid; j < count; j += NTHREADS) {
        float2 c = __ldg(&cxy[j]);
        float  z = __ldg(&cz[j]);
        float dx = px - c.x;
        float dy = py - c.y;
        float dz = pz - z;
        float s2 = fmaf(dx, dx, fmaf(dy, dy, dz * dz));   // squared chord
        if (s2 < s2_th) {                                  // rare path
            float sa = fminf(0.5f * __fsqrt_rn(s2), 1.0f);
            float l  = (-8.0f * EARTH_R) * asinf(sa);      // -4 * dist
            if (l > m) {
                s = s * __expf(m - l) + 1.0f;
                m = l;
                // new skip threshold: keep l >= m - T  <=>  d <= (T - m)/4
                float phi = (LSE_T - m) * (0.25f / (2.0f * EARTH_R));
                if (phi < 1.5707963f) {
                    float sp = __sinf(phi);
                    s2_th = 4.0f * sp * sp;
                } else {
                    s2_th = 5.0f;
                }
            } else {
                s += __expf(l - m);
            }
        }
    }

    // Warp-level (m, s) pair combine
    #pragma unroll
    for (int off = 16; off > 0; off >>= 1) {
        float mo = __shfl_xor_sync(0xffffffffu, m, off);
        float so = __shfl_xor_sync(0xffffffffu, s, off);
        float mn = fmaxf(m, mo);
        s = s * __expf(m - mn) + so * __expf(mo - mn);
        m = mn;
    }

    __shared__ float sh_m[NTHREADS / 32];
    __shared__ float sh_s[NTHREADS / 32];
    const int warp = tid >> 5;
    const int lane = tid & 31;
    if (lane == 0) { sh_m[warp] = m; sh_s[warp] = s; }
    __syncthreads();

    if (tid == 0) {
        float M0 = sh_m[0], S0 = sh_s[0];
        #pragma unroll
        for (int w = 1; w < NTHREADS / 32; ++w) {
            float mo = sh_m[w], so = sh_s[w];
            float mn = fmaxf(M0, mo);
            S0 = S0 * __expf(M0 - mn) + so * __expf(mo - mn);
            M0 = mn;
        }
        float soft = 0.0f;
        if (count > 0) soft = -0.25f * (M0 + __logf(S0));
        g_soft[b]  = soft;
        g_valid[b] = (count > 0) ? 1.0f : 0.0f;
    }

    // ---- fused final reduction: last block to arrive does it ----
    __shared__ int sh_last;
    __threadfence();
    __syncthreads();
    if (tid == 0) {
        int t = atomicAdd(&g_ticket, 1);
        sh_last = (t == gridDim.x - 1) ? 1 : 0;
    }
    __syncthreads();
    if (sh_last) {
        __shared__ float rs[NTHREADS];
        __shared__ float rv[NTHREADS];
        float ss = 0.0f, vv = 0.0f;
        for (int i = tid; i < B_ROWS; i += NTHREADS) {
            ss += g_soft[i];
            vv += g_valid[i];
        }
        rs[tid] = ss;
        rv[tid] = vv;
        __syncthreads();
        #pragma unroll
        for (int off = NTHREADS / 2; off > 0; off >>= 1) {
            if (tid < off) {
                rs[tid] += rs[tid + off];
                rv[tid] += rv[tid + off];
            }
            __syncthreads();
        }
        if (tid == 0) out[0] = rs[0] / fmaxf(rv[0], 1.0f);
    }
}

extern "C" void kernel_launch(void* const* d_in, const int* in_sizes, int n_in,
                              void* d_out, int out_size) {
    // Identify inputs by element count (all four are distinct).
    const float*     preds      = 0;   // 16384
    const float2*    bin_coords = 0;   // 1024000
    const long long* x_vals     = 0;   // 24576
    const long long* bin_counts = 0;   // 125
    for (int i = 0; i < n_in; ++i) {
        switch (in_sizes[i]) {
            case 16384:   preds      = (const float*)d_in[i];     break;
            case 1024000: bin_coords = (const float2*)d_in[i];    break;
            case 24576:   x_vals     = (const long long*)d_in[i]; break;
            case 125:     bin_counts = (const long long*)d_in[i]; break;
        }
    }
    float* out = (float*)d_out;

    precompute_xyz_kernel<<<(NTOT + 255) / 256, 256>>>(bin_coords);
    softbin_main_kernel<<<B_ROWS, NTHREADS>>>(preds, x_vals, bin_counts, out);
}

// round 5
// speedup vs baseline: 1.1700x; 1.1700x over previous
#include <cuda_runtime.h>

#define B_ROWS   8192
#define NBINS    125
#define M_CAND   4096
#define NTOT     (NBINS * M_CAND)
#define NTHREADS 256
#define NWARPS   (NTHREADS / 32)
#define EARTH_R  3958.8f
#define DEG2RAD  0.017453292519943295f
#define D_WINDOW 5.0f   /* logit window 20 => 20/4 = 5 miles; exp(-20)=2e-9 */

// Static scratch (no allocations allowed)
__device__ float4 g_xyz[NTOT];     // candidate unit vectors (x,y,z,pad)
__device__ float  g_soft [B_ROWS];
__device__ float  g_valid[B_ROWS];
__device__ int    g_ticket;

// ---------------------------------------------------------------------------
// Kernel 1: (lon, lat) deg -> 3D unit vector, padded to float4 for LDG.128.
// ---------------------------------------------------------------------------
__global__ __launch_bounds__(256)
void precompute_xyz_kernel(const float2* __restrict__ bin_coords) {
    int i = blockIdx.x * 256 + threadIdx.x;
    if (i == 0) g_ticket = 0;
    if (i >= NTOT) return;
    float2 c = bin_coords[i];             // (lon, lat) degrees
    float lon = c.x * DEG2RAD;
    float lat = c.y * DEG2RAD;
    float slat, clat, slon, clon;
    __sincosf(lat, &slat, &clat);         // |arg| <= ~0.18 rad: fast path is exact enough
    __sincosf(lon, &slon, &clon);
    g_xyz[i] = make_float4(clat * clon, clat * slon, slat, 0.0f);
}

// ---------------------------------------------------------------------------
// Kernel 2: pass1 min over squared chords (branchless, s2 cached in smem),
// pass2 smem replay with known threshold, fused final reduction.
// ---------------------------------------------------------------------------
__global__ __launch_bounds__(NTHREADS)
void softbin_main_kernel(const float* __restrict__ preds,
                         const long long* __restrict__ x_vals,
                         const long long* __restrict__ bin_counts,
                         float* __restrict__ out) {
    __shared__ float sh_s2[M_CAND];
    __shared__ float sh_red[NWARPS];
    __shared__ float sh_p[3];
    __shared__ int   sh_meta[2];

    const int b    = blockIdx.x;
    const int tid  = threadIdx.x;
    const int warp = tid >> 5;
    const int lane = tid & 31;

    if (tid == 0) {
        long long bin_id = x_vals[b * 3 + 0] * 25 + x_vals[b * 3 + 1] * 5 + x_vals[b * 3 + 2];
        if (bin_id < 0) bin_id = 0;
        if (bin_id >= NBINS) bin_id = NBINS - 1;
        int count = (int)bin_counts[bin_id];
        if (count > M_CAND) count = M_CAND;
        sh_meta[0] = (int)bin_id * M_CAND;
        sh_meta[1] = count;
        float lon = preds[b * 2 + 0] * DEG2RAD;
        float lat = preds[b * 2 + 1] * DEG2RAD;
        float slat, clat, slon, clon;
        sincosf(lat, &slat, &clat);       // accurate: once per row, larger args
        sincosf(lon, &slon, &clon);
        sh_p[0] = clat * clon;
        sh_p[1] = clat * slon;
        sh_p[2] = slat;
    }
    __syncthreads();

    const int   base  = sh_meta[0];
    const int   count = sh_meta[1];
    const float px = sh_p[0], py = sh_p[1], pz = sh_p[2];
    const float4* __restrict__ cand = g_xyz + base;

    // ---- pass 1: branchless min of squared chord; cache s2 in smem ----
    float s2min = 4.0e9f;
    #pragma unroll 4
    for (int j = tid; j < count; j += NTHREADS) {
        float4 c = __ldg(&cand[j]);
        float dx = px - c.x;
        float dy = py - c.y;
        float dz = pz - c.z;
        float s2 = fmaf(dx, dx, fmaf(dy, dy, dz * dz));
        sh_s2[j] = s2;
        s2min = fminf(s2min, s2);
    }
    #pragma unroll
    for (int off = 16; off > 0; off >>= 1)
        s2min = fminf(s2min, __shfl_xor_sync(0xffffffffu, s2min, off));
    if (lane == 0) sh_red[warp] = s2min;
    __syncthreads();
    float s2_blk = sh_red[0];
    #pragma unroll
    for (int w = 1; w < NWARPS; ++w) s2_blk = fminf(s2_blk, sh_red[w]);

    // d_min and chord^2 threshold for d <= d_min + 5 miles
    const float d_min = (2.0f * EARTH_R) * asinf(fminf(0.5f * __fsqrt_rn(s2_blk), 1.0f));
    float phi = (d_min + D_WINDOW) * (0.5f / EARTH_R);
    float s2_th;
    if (phi < 1.5707963f) {
        float sp = sinf(phi);
        s2_th = 4.0f * sp * sp * 1.000001f;   // widen for rounding
    } else {
        s2_th = 5.0f;
    }

    // ---- pass 2: replay from smem; transcendentals only inside window ----
    float ssum = 0.0f;
    for (int j = tid; j < count; j += NTHREADS) {
        float s2 = sh_s2[j];
        if (s2 <= s2_th) {
            float d = (2.0f * EARTH_R) * asinf(fminf(0.5f * __fsqrt_rn(s2), 1.0f));
            ssum += __expf(4.0f * (d_min - d));   // includes min element: exp(0)=1
        }
    }
    #pragma unroll
    for (int off = 16; off > 0; off >>= 1)
        ssum += __shfl_xor_sync(0xffffffffu, ssum, off);
    __syncthreads();              // sh_red reuse
    if (lane == 0) sh_red[warp] = ssum;
    __syncthreads();

    if (tid == 0) {
        float S = sh_red[0];
        #pragma unroll
        for (int w = 1; w < NWARPS; ++w) S += sh_red[w];
        // soft_min = -tau*(m + log S), m = -4*d_min, tau = 0.25
        float soft = (count > 0) ? (d_min - 0.25f * logf(S)) : 0.0f;
        g_soft[b]  = soft;
        g_valid[b] = (count > 0) ? 1.0f : 0.0f;
    }

    // ---- fused final reduction: last block to arrive finishes ----
    __shared__ int sh_last;
    __threadfence();
    __syncthreads();
    if (tid == 0) {
        int t = atomicAdd(&g_ticket, 1);
        sh_last = (t == gridDim.x - 1) ? 1 : 0;
    }
    __syncthreads();
    if (sh_last) {
        __shared__ float rs[NTHREADS];
        __shared__ float rv[NTHREADS];
        float ss = 0.0f, vv = 0.0f;
        for (int i = tid; i < B_ROWS; i += NTHREADS) {
            ss += g_soft[i];
            vv += g_valid[i];
        }
        rs[tid] = ss;
        rv[tid] = vv;
        __syncthreads();
        #pragma unroll
        for (int off = NTHREADS / 2; off > 0; off >>= 1) {
            if (tid < off) {
                rs[tid] += rs[tid + off];
                rv[tid] += rv[tid + off];
            }
            __syncthreads();
        }
        if (tid == 0) out[0] = rs[0] / fmaxf(rv[0], 1.0f);
    }
}

extern "C" void kernel_launch(void* const* d_in, const int* in_sizes, int n_in,
                              void* d_out, int out_size) {
    // Identify inputs by element count (all four are distinct).
    const float*     preds      = 0;   // 16384
    const float2*    bin_coords = 0;   // 1024000
    const long long* x_vals     = 0;   // 24576
    const long long* bin_counts = 0;   // 125
    for (int i = 0; i < n_in; ++i) {
        switch (in_sizes[i]) {
            case 16384:   preds      = (const float*)d_in[i];     break;
            case 1024000: bin_coords = (const float2*)d_in[i];    break;
            case 24576:   x_vals     = (const long long*)d_in[i]; break;
            case 125:     bin_counts = (const long long*)d_in[i]; break;
        }
    }
    float* out = (float*)d_out;

    precompute_xyz_kernel<<<(NTOT + 255) / 256, 256>>>(bin_coords);
    softbin_main_kernel<<<B_ROWS, NTHREADS>>>(preds, x_vals, bin_counts, out);
}

// round 8
// speedup vs baseline: 1.2081x; 1.0325x over previous
#include <cuda_runtime.h>

#define B_ROWS   8192
#define NBINS    125
#define M_CAND   4096
#define NTOT     (NBINS * M_CAND)
#define NTHREADS 256
#define NWARPS   8
#define EARTH_R  3958.8f
#define DEG2RAD  0.017453292519943295f
#define D_WINDOW 5.0f   /* logit window 20 -> 5 miles; exp(-20)=2e-9 */

// Static scratch (no allocations allowed)
__device__ float4 g_xyz[NTOT];     // candidate unit vectors (x,y,z,0)
__device__ float4 g_rowv[B_ROWS];  // row unit vectors (x,y,z,0)
__device__ int2   g_meta[B_ROWS];  // (base index, count) per row
__device__ float  g_soft [B_ROWS];
__device__ float  g_valid[B_ROWS];
__device__ int    g_ticket;

// ---------------------------------------------------------------------------
// Kernel 1 (merged prep): candidates -> unit vectors; rows -> unit vector +
// (base, count) meta; ticket reset.
// ---------------------------------------------------------------------------
__global__ __launch_bounds__(256)
void prep_kernel(const float2* __restrict__ bin_coords,
                 const float* __restrict__ preds,
                 const long long* __restrict__ x_vals,
                 const long long* __restrict__ bin_counts) {
    int i = blockIdx.x * 256 + threadIdx.x;
    if (i == 0) g_ticket = 0;
    if (i < NTOT) {
        float2 c = bin_coords[i];             // (lon, lat) degrees
        float lon = c.x * DEG2RAD;
        float lat = c.y * DEG2RAD;
        float slat, clat, slon, clon;
        __sincosf(lat, &slat, &clat);
        __sincosf(lon, &slon, &clon);
        g_xyz[i] = make_float4(clat * clon, clat * slon, slat, 0.0f);
    } else if (i < NTOT + B_ROWS) {
        int b = i - NTOT;
        long long bin_id = x_vals[b * 3 + 0] * 25 + x_vals[b * 3 + 1] * 5 + x_vals[b * 3 + 2];
        if (bin_id < 0) bin_id = 0;
        if (bin_id >= NBINS) bin_id = NBINS - 1;
        int count = (int)bin_counts[bin_id];
        if (count < 0) count = 0;
        if (count > M_CAND) count = M_CAND;
        float lon = preds[b * 2 + 0] * DEG2RAD;
        float lat = preds[b * 2 + 1] * DEG2RAD;
        float slat, clat, slon, clon;
        sincosf(lat, &slat, &clat);           // libm accuracy once per row
        sincosf(lon, &slon, &clon);
        g_rowv[b] = make_float4(clat * clon, clat * slon, slat, 0.0f);
        g_meta[b] = make_int2((int)bin_id * M_CAND, count);
    }
}

// ---------------------------------------------------------------------------
// Kernel 2: pass1 branchless min of squared chords (cached in smem),
// pass2 scalar unrolled replay with known threshold, fused final reduction.
// ---------------------------------------------------------------------------
__global__ __launch_bounds__(NTHREADS)
void softbin_main_kernel(float* __restrict__ out) {
    __shared__ float sh_s2[M_CAND];
    __shared__ float sh_red[NWARPS];

    const int b    = blockIdx.x;
    const int tid  = threadIdx.x;
    const int warp = tid >> 5;
    const int lane = tid & 31;

    const int2  mt = g_meta[b];
    const int base = mt.x;
    const int count = mt.y;
    const float4 rv = g_rowv[b];              // broadcast LDG.128
    const float px = rv.x, py = rv.y, pz = rv.z;

    const float4* __restrict__ cand = g_xyz + base;

    // ---- pass 1: branchless min of squared chord; cache s2 in smem ----
    float s2min = 1.0e30f;
    #pragma unroll 4
    for (int j = tid; j < count; j += NTHREADS) {
        float4 c = __ldg(&cand[j]);
        float dx = px - c.x;
        float dy = py - c.y;
        float dz = pz - c.z;
        float s2 = fmaf(dx, dx, fmaf(dy, dy, dz * dz));
        sh_s2[j] = s2;
        s2min = fminf(s2min, s2);
    }
    #pragma unroll
    for (int off = 16; off > 0; off >>= 1)
        s2min = fminf(s2min, __shfl_xor_sync(0xffffffffu, s2min, off));
    if (lane == 0) sh_red[warp] = s2min;
    __syncthreads();

    float s2b = sh_red[0];
    #pragma unroll
    for (int w = 1; w < NWARPS; ++w) s2b = fminf(s2b, sh_red[w]);

    const float d_min = (2.0f * EARTH_R) * asinf(fminf(0.5f * __fsqrt_rn(s2b), 1.0f));
    float phi = (d_min + D_WINDOW) * (0.5f / EARTH_R);
    float s2_th;
    if (phi < 1.5707963f) {
        float sp = sinf(phi);
        s2_th = 4.0f * sp * sp * 1.000001f;
    } else {
        s2_th = 5.0f;
    }

    // ---- pass 2: unrolled scalar replay; transcendentals only in window ----
    float ssum = 0.0f;
    const float K   = -8.0f * EARTH_R;   // 4*(d_min-d) = 4*d_min + K*asin(.)
    const float dm4 = 4.0f * d_min;
    #pragma unroll 4
    for (int j = tid; j < count; j += NTHREADS) {
        float s2 = sh_s2[j];
        if (s2 <= s2_th) {
            ssum += __expf(fmaf(K, asinf(fminf(0.5f * __fsqrt_rn(s2), 1.0f)), dm4));
        }
    }
    #pragma unroll
    for (int off = 16; off > 0; off >>= 1)
        ssum += __shfl_xor_sync(0xffffffffu, ssum, off);
    __syncthreads();                   // sh_red reuse
    if (lane == 0) sh_red[warp] = ssum;
    __syncthreads();

    if (tid == 0) {
        float S = sh_red[0];
        #pragma unroll
        for (int w = 1; w < NWARPS; ++w) S += sh_red[w];
        // soft_min = -tau*(m + log S), m = -4*d_min, tau = 0.25
        float soft = (count > 0) ? (d_min - 0.25f * logf(S)) : 0.0f;
        g_soft[b]  = soft;
        g_valid[b] = (count > 0) ? 1.0f : 0.0f;
    }

    // ---- fused final reduction: last block to arrive finishes ----
    __shared__ int sh_last;
    __threadfence();
    __syncthreads();
    if (tid == 0) {
        int t = atomicAdd(&g_ticket, 1);
        sh_last = (t == gridDim.x - 1) ? 1 : 0;
    }
    __syncthreads();
    if (sh_last) {
        __shared__ float rs[NTHREADS];
        __shared__ float rvv[NTHREADS];
        float ss = 0.0f, vv = 0.0f;
        for (int i = tid; i < B_ROWS; i += NTHREADS) {
            ss += g_soft[i];
            vv += g_valid[i];
        }
        rs[tid] = ss;
        rvv[tid] = vv;
        __syncthreads();
        #pragma unroll
        for (int off = NTHREADS / 2; off > 0; off >>= 1) {
            if (tid < off) {
                rs[tid]  += rs[tid + off];
                rvv[tid] += rvv[tid + off];
            }
            __syncthreads();
        }
        if (tid == 0) out[0] = rs[0] / fmaxf(rvv[0], 1.0f);
    }
}

extern "C" void kernel_launch(void* const* d_in, const int* in_sizes, int n_in,
                              void* d_out, int out_size) {
    // Identify inputs by element count (all four are distinct).
    const float*     preds      = 0;   // 16384
    const float2*    bin_coords = 0;   // 1024000
    const long long* x_vals     = 0;   // 24576
    const long long* bin_counts = 0;   // 125
    for (int i = 0; i < n_in; ++i) {
        switch (in_sizes[i]) {
            case 16384:   preds      = (const float*)d_in[i];     break;
            case 1024000: bin_coords = (const float2*)d_in[i];    break;
            case 24576:   x_vals     = (const long long*)d_in[i]; break;
            case 125:     bin_counts = (const long long*)d_in[i]; break;
        }
    }
    float* out = (float*)d_out;

    const int prep_total = NTOT + B_ROWS;
    prep_kernel<<<(prep_total + 255) / 256, 256>>>(bin_coords, preds, x_vals, bin_counts);
    softbin_main_kernel<<<B_ROWS, NTHREADS>>>(out);
}

// round 9
// speedup vs baseline: 1.2551x; 1.0389x over previous
#include <cuda_runtime.h>

#define B_ROWS   8192
#define NBINS    125
#define M_CAND   4096
#define NTOT     (NBINS * M_CAND)
#define NTHREADS 256
#define NWARPS   8
#define EARTH_R  3958.8f
#define DEG2RAD  0.017453292519943295f
#define D_WINDOW 6.0f   /* logit window 24 -> 6 miles; exp(-24)=4e-11 */
#define LOG2E    1.4426950408889634f

// Static scratch (no allocations allowed)
__device__ float4 g_xyz[NTOT];     // candidate unit vectors (x,y,z,0)
__device__ float4 g_rowv[B_ROWS];  // row unit vectors (x,y,z,0)
__device__ int2   g_meta[B_ROWS];  // (base index, count) per row
__device__ float  g_soft [B_ROWS];
__device__ float  g_valid[B_ROWS];
__device__ int    g_ticket;

// ---------------------------------------------------------------------------
// Kernel 1 (merged prep): candidates -> unit vectors; rows -> unit vector +
// (base, count) meta; ticket reset.
// ---------------------------------------------------------------------------
__global__ __launch_bounds__(256)
void prep_kernel(const float2* __restrict__ bin_coords,
                 const float* __restrict__ preds,
                 const long long* __restrict__ x_vals,
                 const long long* __restrict__ bin_counts) {
    int i = blockIdx.x * 256 + threadIdx.x;
    if (i == 0) g_ticket = 0;
    if (i < NTOT) {
        float2 c = bin_coords[i];             // (lon, lat) degrees
        float lon = c.x * DEG2RAD;
        float lat = c.y * DEG2RAD;
        float slat, clat, slon, clon;
        __sincosf(lat, &slat, &clat);
        __sincosf(lon, &slon, &clon);
        g_xyz[i] = make_float4(clat * clon, clat * slon, slat, 0.0f);
    } else if (i < NTOT + B_ROWS) {
        int b = i - NTOT;
        long long bin_id = x_vals[b * 3 + 0] * 25 + x_vals[b * 3 + 1] * 5 + x_vals[b * 3 + 2];
        if (bin_id < 0) bin_id = 0;
        if (bin_id >= NBINS) bin_id = NBINS - 1;
        int count = (int)bin_counts[bin_id];
        if (count < 0) count = 0;
        if (count > M_CAND) count = M_CAND;
        float lon = preds[b * 2 + 0] * DEG2RAD;
        float lat = preds[b * 2 + 1] * DEG2RAD;
        float slat, clat, slon, clon;
        sincosf(lat, &slat, &clat);           // libm accuracy once per row
        sincosf(lon, &slon, &clon);
        g_rowv[b] = make_float4(clat * clon, clat * slon, slat, 0.0f);
        g_meta[b] = make_int2((int)bin_id * M_CAND, count);
    }
}

// ---------------------------------------------------------------------------
// Kernel 2: pass1 min of squared chords (cached in smem), pass2 vectorized
// replay using exact-slope linearized asin, fused final reduction.
// ---------------------------------------------------------------------------
__global__ __launch_bounds__(NTHREADS)
void softbin_main_kernel(float* __restrict__ out) {
    __shared__ __align__(16) float sh_s2[M_CAND];
    __shared__ float sh_red[NWARPS];

    const int b    = blockIdx.x;
    const int tid  = threadIdx.x;
    const int warp = tid >> 5;
    const int lane = tid & 31;

    const int2  mt  = g_meta[b];
    const int base  = mt.x;
    const int count = mt.y;
    const float4 rv = g_rowv[b];              // broadcast LDG.128
    const float px = rv.x, py = rv.y, pz = rv.z;

    const float4* __restrict__ cand = g_xyz + base;

    // ---- pass 1: min of squared chord; cache s2 in smem ----
    float s2min = 1.0e30f;
    #pragma unroll 4
    for (int j = tid; j < count; j += NTHREADS) {
        float4 c = __ldg(&cand[j]);
        float dx = px - c.x;
        float dy = py - c.y;
        float dz = pz - c.z;
        float s2 = fmaf(dx, dx, fmaf(dy, dy, dz * dz));
        sh_s2[j] = s2;
        s2min = fminf(s2min, s2);
    }
    // pad tail to multiple of 4 so pass2 can use unguarded float4 reads
    const int cup = (count + 3) & ~3;
    if (tid < cup - count) sh_s2[count + tid] = 1.0e30f;

    #pragma unroll
    for (int off = 16; off > 0; off >>= 1)
        s2min = fminf(s2min, __shfl_xor_sync(0xffffffffu, s2min, off));
    if (lane == 0) sh_red[warp] = s2min;
    __syncthreads();                           // also publishes sh_s2

    float s2b = sh_red[0];
    #pragma unroll
    for (int w = 1; w < NWARPS; ++w) s2b = fminf(s2b, sh_red[w]);

    // Exact local linearization of d(c) = 2R asin(c/2) at c_min.
    const float c_min = __fsqrt_rn(s2b);
    const float half  = fminf(0.5f * c_min, 1.0f);
    const float d_min = (2.0f * EARTH_R) * asinf(half);
    const float denom = fmaxf(fmaf(-half, half, 1.0f), 1.0e-12f);
    const float slope = EARTH_R * rsqrtf(denom);       // dd/dc at c_min
    // logit(c) - logit(c_min) = -4*slope*(c - c_min); in log2 units:
    const float K_L = -4.0f * slope * LOG2E;
    const float B_L = -K_L * c_min;
    // chord^2 threshold for d <= d_min + D_WINDOW (linear chord estimate)
    const float c_th  = c_min + D_WINDOW / slope;
    const float s2_th = c_th * c_th * 1.0001f;

    // ---- pass 2: float4 replay; sqrt/exp only inside window ----
    float ssum = 0.0f;
    const float4* __restrict__ s2v = (const float4*)sh_s2;
    const int n4 = cup >> 2;
    #pragma unroll 2
    for (int q = tid; q < n4; q += NTHREADS) {
        float4 v = s2v[q];
        if (v.x <= s2_th) ssum += exp2f(fmaf(K_L, __fsqrt_rn(v.x), B_L));
        if (v.y <= s2_th) ssum += exp2f(fmaf(K_L, __fsqrt_rn(v.y), B_L));
        if (v.z <= s2_th) ssum += exp2f(fmaf(K_L, __fsqrt_rn(v.z), B_L));
        if (v.w <= s2_th) ssum += exp2f(fmaf(K_L, __fsqrt_rn(v.w), B_L));
    }
    #pragma unroll
    for (int off = 16; off > 0; off >>= 1)
        ssum += __shfl_xor_sync(0xffffffffu, ssum, off);
    __syncthreads();                   // sh_red reuse
    if (lane == 0) sh_red[warp] = ssum;
    __syncthreads();

    if (tid == 0) {
        float S = sh_red[0];
        #pragma unroll
        for (int w = 1; w < NWARPS; ++w) S += sh_red[w];
        // soft_min = -tau*(m + log S), m = -4*d_min, tau = 0.25
        float soft = (count > 0) ? (d_min - 0.25f * logf(S)) : 0.0f;
        g_soft[b]  = soft;
        g_valid[b] = (count > 0) ? 1.0f : 0.0f;
    }

    // ---- fused final reduction: last block to arrive finishes ----
    __shared__ int sh_last;
    __threadfence();
    __syncthreads();
    if (tid == 0) {
        int t = atomicAdd(&g_ticket, 1);
        sh_last = (t == gridDim.x - 1) ? 1 : 0;
    }
    __syncthreads();
    if (sh_last) {
        __shared__ float rs[NTHREADS];
        __shared__ float rvv[NTHREADS];
        float ss = 0.0f, vv = 0.0f;
        for (int i = tid; i < B_ROWS; i += NTHREADS) {
            ss += g_soft[i];
            vv += g_valid[i];
        }
        rs[tid] = ss;
        rvv[tid] = vv;
        __syncthreads();
        #pragma unroll
        for (int off = NTHREADS / 2; off > 0; off >>= 1) {
            if (tid < off) {
                rs[tid]  += rs[tid + off];
                rvv[tid] += rvv[tid + off];
            }
            __syncthreads();
        }
        if (tid == 0) out[0] = rs[0] / fmaxf(rvv[0], 1.0f);
    }
}

extern "C" void kernel_launch(void* const* d_in, const int* in_sizes, int n_in,
                              void* d_out, int out_size) {
    // Identify inputs by element count (all four are distinct).
    const float*     preds      = 0;   // 16384
    const float2*    bin_coords = 0;   // 1024000
    const long long* x_vals     = 0;   // 24576
    const long long* bin_counts = 0;   // 125
    for (int i = 0; i < n_in; ++i) {
        switch (in_sizes[i]) {
            case 16384:   preds      = (const float*)d_in[i];     break;
            case 1024000: bin_coords = (const float2*)d_in[i];    break;
            case 24576:   x_vals     = (const long long*)d_in[i]; break;
            case 125:     bin_counts = (const long long*)d_in[i]; break;
        }
    }
    float* out = (float*)d_out;

    const int prep_total = NTOT + B_ROWS;
    prep_kernel<<<(prep_total + 255) / 256, 256>>>(bin_coords, preds, x_vals, bin_counts);
    softbin_main_kernel<<<B_ROWS, NTHREADS>>>(out);
}